// round 8
// baseline (speedup 1.0000x reference)
#include <cuda_runtime.h>
#include <cuda_bf16.h>
#include <cstdint>
#include <math.h>

// Shape fixed by reference: N=4096, T=64, D=1024, fp32.
#define Nn 4096
#define Tt 64
#define Dd 1024
#define THREADS 256          // thread tid owns float4 at d-offset 4*tid
#define TILE 8               // t-rows per tile (32 KB contiguous chunk of h[n])
#define TILE_BYTES (TILE * Dd * 4)   // 32768

// smem layout (bytes):
//   [0,16)      mbar[2]
//   [16,2064)   part[64][8] : per-n partial dots, row-major (row*8+warp)
//   [2176, 2176+2*32768) double buffers (128B aligned)
#define SMEM_MBAR_OFF  0
#define SMEM_PART_OFF  16
#define SMEM_BUF_OFF   2176
#define SMEM_BYTES     (SMEM_BUF_OFF + 2 * TILE_BYTES)   // 67712 -> 3 CTA/SM

__device__ __forceinline__ uint32_t smem_u32(const void* p) {
    uint32_t a;
    asm("{ .reg .u64 t; cvta.to.shared.u64 t, %1; cvt.u32.u64 %0, t; }" : "=r"(a) : "l"(p));
    return a;
}
__device__ __forceinline__ void mbar_init(uint32_t mbar, uint32_t count) {
    asm volatile("mbarrier.init.shared.b64 [%0], %1;" :: "r"(mbar), "r"(count) : "memory");
}
__device__ __forceinline__ void mbar_expect_tx(uint32_t mbar, uint32_t bytes) {
    asm volatile("mbarrier.arrive.expect_tx.shared.b64 _, [%0], %1;" :: "r"(mbar), "r"(bytes) : "memory");
}
__device__ __forceinline__ void bulk_copy_g2s(uint32_t dst_smem, const void* src_gmem,
                                              uint32_t bytes, uint32_t mbar) {
    asm volatile(
        "cp.async.bulk.shared::cluster.global.mbarrier::complete_tx::bytes [%0], [%1], %2, [%3];"
        :: "r"(dst_smem), "l"(src_gmem), "r"(bytes), "r"(mbar) : "memory");
}
__device__ __forceinline__ void mbar_wait_parity(uint32_t mbar, uint32_t parity) {
    uint32_t done;
    asm volatile(
        "{\n\t.reg .pred p;\n\t"
        "mbarrier.try_wait.parity.acquire.cta.shared::cta.b64 p, [%1], %2;\n\t"
        "selp.b32 %0, 1, 0, p;\n\t}"
        : "=r"(done) : "r"(mbar), "r"(parity) : "memory");
    if (!done) {
        asm volatile(
            "{\n\t.reg .pred P1;\n\t"
            "WL_%=:\n\t"
            "mbarrier.try_wait.parity.acquire.cta.shared::cta.b64 P1, [%0], %1, 0x989680;\n\t"
            "@P1 bra.uni WD_%=;\n\t"
            "bra.uni WL_%=;\n\t"
            "WD_%=:\n\t}"
            :: "r"(mbar), "r"(parity) : "memory");
    }
}

__global__ __launch_bounds__(THREADS, 3)
void attn_pool_persist2(const float* __restrict__ h,
                        const float* __restrict__ w_score,
                        float* __restrict__ out_pooled,
                        float* __restrict__ out_alpha)
{
    extern __shared__ __align__(16) char smem_raw[];
    float* part = (float*)(smem_raw + SMEM_PART_OFF);   // part[row*8 + warp], row in [0,64)
    const uint32_t mbar0 = smem_u32(smem_raw + SMEM_MBAR_OFF);
    const uint32_t mbar1 = mbar0 + 8;
    const uint32_t buf_s = smem_u32(smem_raw + SMEM_BUF_OFF);
    const float4* buf[2] = { (const float4*)(smem_raw + SMEM_BUF_OFF),
                             (const float4*)(smem_raw + SMEM_BUF_OFF + TILE_BYTES) };

    const int tid  = threadIdx.x;
    const int warp = tid >> 5;
    const int lane = tid & 31;
    const int bid  = blockIdx.x;
    const int ncta = gridDim.x;

    const float4 wv = __ldg((const float4*)w_score + tid);

    const int n_count = (bid < Nn) ? ((Nn - 1 - bid) / ncta + 1) : 0;
    const int total_f = n_count * 8;   // flat tile stream (multiple of 8)
    if (total_f == 0) return;

    // flat tile f -> gmem byte pointer
    #define SRC_OF(f) ((const char*)h + \
        ((size_t)(bid + ((f) >> 3) * ncta) * (Tt * Dd) + (size_t)((f) & 7) * (TILE * Dd)) * 4)

    if (tid == 0) {
        mbar_init(mbar0, 1);
        mbar_init(mbar1, 1);
    }
    __syncthreads();
    if (tid == 0) {
        mbar_expect_tx(mbar0, TILE_BYTES);
        bulk_copy_g2s(buf_s, SRC_OF(0), TILE_BYTES, mbar0);
        if (total_f > 1) {
            mbar_expect_tx(mbar1, TILE_BYTES);
            bulk_copy_g2s(buf_s + TILE_BYTES, SRC_OF(1), TILE_BYTES, mbar1);
        }
    }

    float m = -INFINITY, Z = 0.0f;               // redundant in all threads
    float4 acc = make_float4(0.f, 0.f, 0.f, 0.f);

    for (int f = 0; f < total_f; f++) {
        const int b        = f & 1;
        const uint32_t mb  = b ? mbar1 : mbar0;
        const uint32_t par = (f >> 1) & 1;
        const float4* bp   = buf[b];

        mbar_wait_parity(mb, par);

        // ---- slab into regs (8x LDS.128, conflict-free) ----
        float4 v[TILE];
        #pragma unroll
        for (int i = 0; i < TILE; i++)
            v[i] = bp[i * 256 + tid];

        // ---- partial dots + full butterfly; lane0 stores per-warp sums ----
        float pd[TILE];
        #pragma unroll
        for (int i = 0; i < TILE; i++)
            pd[i] = v[i].x * wv.x + v[i].y * wv.y + v[i].z * wv.z + v[i].w * wv.w;
        #pragma unroll
        for (int i = 0; i < TILE; i++) {
            #pragma unroll
            for (int off = 16; off > 0; off >>= 1)
                pd[i] += __shfl_xor_sync(0xFFFFFFFFu, pd[i], off);
        }
        if (lane == 0) {
            #pragma unroll
            for (int i = 0; i < TILE; i++)
                part[((f & 7) * TILE + i) * 8 + warp] = pd[i];
        }
        __syncthreads();   // part ready, slab consumed into regs

        // ---- refill this buffer for tile f+2 (crosses n boundaries) ----
        if (tid == 0 && f + 2 < total_f) {
            mbar_expect_tx(mb, TILE_BYTES);
            bulk_copy_g2s(buf_s + b * TILE_BYTES, SRC_OF(f + 2), TILE_BYTES, mb);
        }

        // ---- assemble 8 scores (broadcast LDS.128) ----
        const float4* p4 = (const float4*)part + (f & 7) * 16;   // 8 rows x 8 floats
        float s[TILE];
        #pragma unroll
        for (int i = 0; i < TILE; i++) {
            float4 a = p4[i * 2], bq = p4[i * 2 + 1];
            s[i] = (a.x + a.y) + (a.z + a.w) + (bq.x + bq.y) + (bq.z + bq.w);
        }

        // ---- redundant online softmax ----
        float tmax = s[0];
        #pragma unroll
        for (int i = 1; i < TILE; i++) tmax = fmaxf(tmax, s[i]);
        const float newm = fmaxf(m, tmax);
        const float sc   = __expf(m - newm);
        float e[TILE], esum = 0.0f;
        #pragma unroll
        for (int i = 0; i < TILE; i++) { e[i] = __expf(s[i] - newm); esum += e[i]; }
        Z = Z * sc + esum;
        m = newm;

        float ax = acc.x * sc, ay = acc.y * sc, az = acc.z * sc, aw = acc.w * sc;
        #pragma unroll
        for (int i = 0; i < TILE; i++) {
            ax = fmaf(e[i], v[i].x, ax);
            ay = fmaf(e[i], v[i].y, ay);
            az = fmaf(e[i], v[i].z, az);
            aw = fmaf(e[i], v[i].w, aw);
        }
        acc = make_float4(ax, ay, az, aw);

        // ---- finalize n every 8 tiles ----
        if ((f & 7) == 7) {
            const float inv  = 1.0f / Z;
            const int   nidx = bid + (f >> 3) * ncta;
            ((float4*)(out_pooled + (size_t)nidx * Dd))[tid] =
                make_float4(acc.x * inv, acc.y * inv, acc.z * inv, acc.w * inv);
            if (tid < Tt) {
                const float4* q = (const float4*)part + tid * 2;
                float4 a = q[0], bq = q[1];
                float srow = (a.x + a.y) + (a.z + a.w) + (bq.x + bq.y) + (bq.z + bq.w);
                out_alpha[(size_t)nidx * Tt + tid] = __expf(srow - m) * inv;
            }
            acc = make_float4(0.f, 0.f, 0.f, 0.f);
            m = -INFINITY;
            Z = 0.0f;
            __syncthreads();   // protect part from next n's writes until alpha is read
        }
    }
    #undef SRC_OF
}

extern "C" void kernel_launch(void* const* d_in, const int* in_sizes, int n_in,
                              void* d_out, int out_size)
{
    const float* h       = (const float*)d_in[0];   // [N, T, D] fp32
    const float* w_score = (const float*)d_in[1];   // [D] fp32

    float* out        = (float*)d_out;
    float* out_pooled = out;                        // [N, D]
    float* out_alpha  = out + (size_t)Nn * Dd;      // [N, T]

    int dev = 0, sms = 148;
    cudaGetDevice(&dev);
    cudaDeviceGetAttribute(&sms, cudaDevAttrMultiProcessorCount, dev);
    int grid = sms * 3;                  // persistent, 3 CTAs/SM
    if (grid > Nn) grid = Nn;

    cudaFuncSetAttribute(attn_pool_persist2,
                         cudaFuncAttributeMaxDynamicSharedMemorySize, SMEM_BYTES);

    attn_pool_persist2<<<grid, THREADS, SMEM_BYTES>>>(h, w_score, out_pooled, out_alpha);
}

// round 9
// speedup vs baseline: 1.0251x; 1.0251x over previous
#include <cuda_runtime.h>
#include <cuda_bf16.h>
#include <cstdint>
#include <math.h>

// Shape fixed by reference: N=4096, T=64, D=1024, fp32.
#define Nn 4096
#define Tt 64
#define Dd 1024
#define THREADS 256          // 8 warps; warp w owns tile-row w for scoring
#define TILE 8               // t-rows per tile (32 KB contiguous chunk of h[n])
#define TILE_BYTES (TILE * Dd * 4)   // 32768

// smem layout (bytes):
//   [0,16)      mbar[2]
//   [16,272)    scores_n[64] (unnormalized scores, persists across the 8 tiles of n)
//   [288,4384)  w_smem[1024]
//   [4480, 4480+2*32768) double buffers (128B aligned)
#define SMEM_MBAR_OFF   0
#define SMEM_SCORE_OFF  16
#define SMEM_W_OFF      288
#define SMEM_BUF_OFF    4480
#define SMEM_BYTES      (SMEM_BUF_OFF + 2 * TILE_BYTES)   // 70016 -> 3 CTA/SM

__device__ __forceinline__ uint32_t smem_u32(const void* p) {
    uint32_t a;
    asm("{ .reg .u64 t; cvta.to.shared.u64 t, %1; cvt.u32.u64 %0, t; }" : "=r"(a) : "l"(p));
    return a;
}
__device__ __forceinline__ void mbar_init(uint32_t mbar, uint32_t count) {
    asm volatile("mbarrier.init.shared.b64 [%0], %1;" :: "r"(mbar), "r"(count) : "memory");
}
__device__ __forceinline__ void mbar_expect_tx(uint32_t mbar, uint32_t bytes) {
    asm volatile("mbarrier.arrive.expect_tx.shared.b64 _, [%0], %1;" :: "r"(mbar), "r"(bytes) : "memory");
}
__device__ __forceinline__ void bulk_copy_g2s(uint32_t dst_smem, const void* src_gmem,
                                              uint32_t bytes, uint32_t mbar) {
    asm volatile(
        "cp.async.bulk.shared::cluster.global.mbarrier::complete_tx::bytes [%0], [%1], %2, [%3];"
        :: "r"(dst_smem), "l"(src_gmem), "r"(bytes), "r"(mbar) : "memory");
}
__device__ __forceinline__ void mbar_wait_parity(uint32_t mbar, uint32_t parity) {
    uint32_t done;
    asm volatile(
        "{\n\t.reg .pred p;\n\t"
        "mbarrier.try_wait.parity.acquire.cta.shared::cta.b64 p, [%1], %2;\n\t"
        "selp.b32 %0, 1, 0, p;\n\t}"
        : "=r"(done) : "r"(mbar), "r"(parity) : "memory");
    if (!done) {
        asm volatile(
            "{\n\t.reg .pred P1;\n\t"
            "WL_%=:\n\t"
            "mbarrier.try_wait.parity.acquire.cta.shared::cta.b64 P1, [%0], %1, 0x989680;\n\t"
            "@P1 bra.uni WD_%=;\n\t"
            "bra.uni WL_%=;\n\t"
            "WD_%=:\n\t}"
            :: "r"(mbar), "r"(parity) : "memory");
    }
}

__global__ __launch_bounds__(THREADS, 3)
void attn_pool_rowdot(const float* __restrict__ h,
                      const float* __restrict__ w_score,
                      float* __restrict__ out_pooled,
                      float* __restrict__ out_alpha)
{
    extern __shared__ __align__(16) char smem_raw[];
    float*        scores_n = (float*)(smem_raw + SMEM_SCORE_OFF);   // [64]
    const float4* w4s      = (const float4*)(smem_raw + SMEM_W_OFF);
    const uint32_t mbar0 = smem_u32(smem_raw + SMEM_MBAR_OFF);
    const uint32_t mbar1 = mbar0 + 8;
    const uint32_t buf_s = smem_u32(smem_raw + SMEM_BUF_OFF);
    const float4* buf[2] = { (const float4*)(smem_raw + SMEM_BUF_OFF),
                             (const float4*)(smem_raw + SMEM_BUF_OFF + TILE_BYTES) };

    const int n    = blockIdx.x;
    const int tid  = threadIdx.x;
    const int warp = tid >> 5;
    const int lane = tid & 31;

    const char* src = (const char*)(h + (size_t)n * (Tt * Dd));

    // one-time: w_score -> smem (4 KB) + mbar init
    ((float4*)(smem_raw + SMEM_W_OFF))[tid] = __ldg((const float4*)w_score + tid);
    if (tid == 0) {
        mbar_init(mbar0, 1);
        mbar_init(mbar1, 1);
    }
    __syncthreads();
    if (tid == 0) {
        mbar_expect_tx(mbar0, TILE_BYTES);
        bulk_copy_g2s(buf_s, src, TILE_BYTES, mbar0);
        mbar_expect_tx(mbar1, TILE_BYTES);
        bulk_copy_g2s(buf_s + TILE_BYTES, src + TILE_BYTES, TILE_BYTES, mbar1);
    }

    float m = -INFINITY, Z = 0.0f;               // redundant in all threads
    float4 acc = make_float4(0.f, 0.f, 0.f, 0.f);

    #pragma unroll 1
    for (int f = 0; f < 8; f++) {
        const int b        = f & 1;
        const uint32_t mb  = b ? mbar1 : mbar0;
        const uint32_t par = (f >> 1) & 1;
        const float4* bp   = buf[b];

        mbar_wait_parity(mb, par);

        // ---- pooling slab into regs (tid-slice, 8x LDS.128 conflict-free) ----
        float4 v[TILE];
        #pragma unroll
        for (int i = 0; i < TILE; i++)
            v[i] = bp[i * 256 + tid];

        // ---- warp w computes full dot of tile-row w ----
        // lane sweeps row: float4 index lane + 32*j; w from smem (same addresses)
        {
            const float4* row = bp + warp * 256;
            float d0 = 0.f, d1 = 0.f, d2 = 0.f, d3 = 0.f;
            #pragma unroll
            for (int j = 0; j < 8; j++) {
                const int idx = lane + 32 * j;
                float4 x = row[idx];
                float4 w = w4s[idx];
                d0 = fmaf(x.x, w.x, d0);
                d1 = fmaf(x.y, w.y, d1);
                d2 = fmaf(x.z, w.z, d2);
                d3 = fmaf(x.w, w.w, d3);
            }
            float d = (d0 + d1) + (d2 + d3);
            #pragma unroll
            for (int off = 16; off > 0; off >>= 1)
                d += __shfl_xor_sync(0xFFFFFFFFu, d, off);
            if (lane == 0)
                scores_n[f * TILE + warp] = d;
        }
        __syncthreads();   // scores ready; buffer consumed (v in regs, row reads done)

        // ---- refill this buffer for tile f+2 ----
        if (tid == 0 && f + 2 < 8) {
            mbar_expect_tx(mb, TILE_BYTES);
            bulk_copy_g2s(buf_s + b * TILE_BYTES, src + (size_t)(f + 2) * TILE_BYTES, TILE_BYTES, mb);
        }

        // ---- read 8 scores (2 broadcast LDS.128) ----
        const float4 s0 = *((const float4*)(scores_n + f * TILE));
        const float4 s1 = *((const float4*)(scores_n + f * TILE) + 1);
        float s[TILE] = { s0.x, s0.y, s0.z, s0.w, s1.x, s1.y, s1.z, s1.w };

        // ---- redundant online softmax ----
        float tmax = s[0];
        #pragma unroll
        for (int i = 1; i < TILE; i++) tmax = fmaxf(tmax, s[i]);
        const float newm = fmaxf(m, tmax);
        const float sc   = __expf(m - newm);
        float e[TILE], esum = 0.0f;
        #pragma unroll
        for (int i = 0; i < TILE; i++) { e[i] = __expf(s[i] - newm); esum += e[i]; }
        Z = Z * sc + esum;
        m = newm;

        float ax = acc.x * sc, ay = acc.y * sc, az = acc.z * sc, aw = acc.w * sc;
        #pragma unroll
        for (int i = 0; i < TILE; i++) {
            ax = fmaf(e[i], v[i].x, ax);
            ay = fmaf(e[i], v[i].y, ay);
            az = fmaf(e[i], v[i].z, az);
            aw = fmaf(e[i], v[i].w, aw);
        }
        acc = make_float4(ax, ay, az, aw);
    }

    // ---- finalize ----
    const float inv = 1.0f / Z;
    ((float4*)(out_pooled + (size_t)n * Dd))[tid] =
        make_float4(acc.x * inv, acc.y * inv, acc.z * inv, acc.w * inv);
    if (tid < Tt)
        out_alpha[(size_t)n * Tt + tid] = __expf(scores_n[tid] - m) * inv;
}

extern "C" void kernel_launch(void* const* d_in, const int* in_sizes, int n_in,
                              void* d_out, int out_size)
{
    const float* h       = (const float*)d_in[0];   // [N, T, D] fp32
    const float* w_score = (const float*)d_in[1];   // [D] fp32

    float* out        = (float*)d_out;
    float* out_pooled = out;                        // [N, D]
    float* out_alpha  = out + (size_t)Nn * Dd;      // [N, T]

    cudaFuncSetAttribute(attn_pool_rowdot,
                         cudaFuncAttributeMaxDynamicSharedMemorySize, SMEM_BYTES);

    attn_pool_rowdot<<<Nn, THREADS, SMEM_BYTES>>>(h, w_score, out_pooled, out_alpha);
}

// round 13
// speedup vs baseline: 1.0510x; 1.0253x over previous
#include <cuda_runtime.h>
#include <cuda_bf16.h>
#include <cstdint>
#include <math.h>

// Shape fixed by reference: N=4096, T=64, D=1024, fp32.
#define Nn 4096
#define Tt 64
#define Dd 1024
#define THREADS 256          // 8 warps
#define TILE 4               // t-rows per tile (16 KB chunk); 16 tiles per n
#define NTILES 16
#define NBUF 3
#define TILE_BYTES (TILE * Dd * 4)   // 16384

// smem layout (bytes):
//   [0,24)      mbar[3]
//   [32,544)    part[16][8] : per-tile half-row dot partials (indexed by f — no reuse race)
//   [544,4640)  w_smem[1024]
//   [5120, 5120+3*16384) triple buffers (1024B aligned)
#define SMEM_MBAR_OFF   0
#define SMEM_PART_OFF   32
#define SMEM_W_OFF      544
#define SMEM_BUF_OFF    5120
#define SMEM_BYTES      (SMEM_BUF_OFF + NBUF * TILE_BYTES)   // 54272 -> 4 CTA/SM

__device__ __forceinline__ uint32_t smem_u32(const void* p) {
    uint32_t a;
    asm("{ .reg .u64 t; cvta.to.shared.u64 t, %1; cvt.u32.u64 %0, t; }" : "=r"(a) : "l"(p));
    return a;
}
__device__ __forceinline__ void mbar_init(uint32_t mbar, uint32_t count) {
    asm volatile("mbarrier.init.shared.b64 [%0], %1;" :: "r"(mbar), "r"(count) : "memory");
}
__device__ __forceinline__ void mbar_expect_tx(uint32_t mbar, uint32_t bytes) {
    asm volatile("mbarrier.arrive.expect_tx.shared.b64 _, [%0], %1;" :: "r"(mbar), "r"(bytes) : "memory");
}
__device__ __forceinline__ void bulk_copy_g2s(uint32_t dst_smem, const void* src_gmem,
                                              uint32_t bytes, uint32_t mbar) {
    asm volatile(
        "cp.async.bulk.shared::cluster.global.mbarrier::complete_tx::bytes [%0], [%1], %2, [%3];"
        :: "r"(dst_smem), "l"(src_gmem), "r"(bytes), "r"(mbar) : "memory");
}
__device__ __forceinline__ void mbar_wait_parity(uint32_t mbar, uint32_t parity) {
    uint32_t done;
    asm volatile(
        "{\n\t.reg .pred p;\n\t"
        "mbarrier.try_wait.parity.acquire.cta.shared::cta.b64 p, [%1], %2;\n\t"
        "selp.b32 %0, 1, 0, p;\n\t}"
        : "=r"(done) : "r"(mbar), "r"(parity) : "memory");
    if (!done) {
        asm volatile(
            "{\n\t.reg .pred P1;\n\t"
            "WL_%=:\n\t"
            "mbarrier.try_wait.parity.acquire.cta.shared::cta.b64 P1, [%0], %1, 0x989680;\n\t"
            "@P1 bra.uni WD_%=;\n\t"
            "bra.uni WL_%=;\n\t"
            "WD_%=:\n\t}"
            :: "r"(mbar), "r"(parity) : "memory");
    }
}

__global__ __launch_bounds__(THREADS, 4)
void attn_pool_deep2(const float* __restrict__ h,
                     const float* __restrict__ w_score,
                     float* __restrict__ out_pooled,
                     float* __restrict__ out_alpha)
{
    extern __shared__ __align__(16) char smem_raw[];
    float*        part = (float*)(smem_raw + SMEM_PART_OFF);    // [16][8]
    const float4* w4s  = (const float4*)(smem_raw + SMEM_W_OFF);
    const uint32_t mbar_b = smem_u32(smem_raw + SMEM_MBAR_OFF);
    const uint32_t buf_s  = smem_u32(smem_raw + SMEM_BUF_OFF);

    const int n    = blockIdx.x;
    const int tid  = threadIdx.x;
    const int warp = tid >> 5;
    const int lane = tid & 31;

    const char* src = (const char*)(h + (size_t)n * (Tt * Dd));

    // one-time: w_score -> smem + mbar init
    ((float4*)(smem_raw + SMEM_W_OFF))[tid] = __ldg((const float4*)w_score + tid);
    if (tid == 0) {
        mbar_init(mbar_b,      1);
        mbar_init(mbar_b + 8,  1);
        mbar_init(mbar_b + 16, 1);
    }
    __syncthreads();
    if (tid == 0) {
        #pragma unroll
        for (int p = 0; p < NBUF; p++) {
            mbar_expect_tx(mbar_b + p * 8, TILE_BYTES);
            bulk_copy_g2s(buf_s + p * TILE_BYTES, src + (size_t)p * TILE_BYTES,
                          TILE_BYTES, mbar_b + p * 8);
        }
    }

    float m = -INFINITY, Z = 0.0f;               // redundant in all threads
    float4 acc = make_float4(0.f, 0.f, 0.f, 0.f);

    int b = 0;
    #pragma unroll 1
    for (int f = 0; f < NTILES; f++) {
        const uint32_t mb  = mbar_b + b * 8;
        const int      par = (f / NBUF) & 1;     // parity of buffer b's current use
        const float4*  bp  = (const float4*)(smem_raw + SMEM_BUF_OFF + b * TILE_BYTES);

        mbar_wait_parity(mb, par);

        // ---- pooling slab into regs (tid-slice, 4x LDS.128 conflict-free) ----
        float4 v[TILE];
        #pragma unroll
        for (int i = 0; i < TILE; i++)
            v[i] = bp[i * 256 + tid];

        // ---- warp w: half-row dot of row (w>>1), half (w&1) ----
        {
            const int row  = warp >> 1;
            const int half = warp & 1;
            const float4* rowp = bp + row * 256 + half * 128;
            const float4* wp   = w4s + half * 128;
            float d0 = 0.f, d1 = 0.f, d2 = 0.f, d3 = 0.f;
            #pragma unroll
            for (int j = 0; j < 4; j++) {
                const int idx = lane + 32 * j;
                float4 x = rowp[idx];
                float4 w = wp[idx];
                d0 = fmaf(x.x, w.x, d0);
                d1 = fmaf(x.y, w.y, d1);
                d2 = fmaf(x.z, w.z, d2);
                d3 = fmaf(x.w, w.w, d3);
            }
            float d = (d0 + d1) + (d2 + d3);
            #pragma unroll
            for (int off = 16; off > 0; off >>= 1)
                d += __shfl_xor_sync(0xFFFFFFFFu, d, off);
            if (lane == 0)
                part[f * 8 + row * 2 + half] = d;   // distinct address per tile: no reuse race
        }
        __syncthreads();   // part[f] ready; all buffer-b reads complete

        // ---- refill this buffer for tile f+3 (2 tile-periods of slack) ----
        if (tid == 0 && f + NBUF < NTILES) {
            mbar_expect_tx(mb, TILE_BYTES);
            bulk_copy_g2s(buf_s + b * TILE_BYTES,
                          src + (size_t)(f + NBUF) * TILE_BYTES, TILE_BYTES, mb);
        }

        // ---- assemble 4 scores (2 broadcast LDS.128) ----
        const float4 p0 = *((const float4*)(part + f * 8));
        const float4 p1 = *((const float4*)(part + f * 8) + 1);
        float s[TILE] = { p0.x + p0.y, p0.z + p0.w, p1.x + p1.y, p1.z + p1.w };

        // ---- redundant online softmax ----
        const float tmax = fmaxf(fmaxf(s[0], s[1]), fmaxf(s[2], s[3]));
        const float newm = fmaxf(m, tmax);
        const float sc   = __expf(m - newm);
        float e[TILE], esum = 0.0f;
        #pragma unroll
        for (int i = 0; i < TILE; i++) { e[i] = __expf(s[i] - newm); esum += e[i]; }
        Z = Z * sc + esum;
        m = newm;

        float ax = acc.x * sc, ay = acc.y * sc, az = acc.z * sc, aw = acc.w * sc;
        #pragma unroll
        for (int i = 0; i < TILE; i++) {
            ax = fmaf(e[i], v[i].x, ax);
            ay = fmaf(e[i], v[i].y, ay);
            az = fmaf(e[i], v[i].z, az);
            aw = fmaf(e[i], v[i].w, aw);
        }
        acc = make_float4(ax, ay, az, aw);

        if (++b == NBUF) b = 0;
    }

    // ---- finalize ----
    const float inv = 1.0f / Z;
    ((float4*)(out_pooled + (size_t)n * Dd))[tid] =
        make_float4(acc.x * inv, acc.y * inv, acc.z * inv, acc.w * inv);
    // alpha from part: score[t] = part[(t>>2)*8 + (t&3)*2] + part[(t>>2)*8 + (t&3)*2 + 1]
    if (tid < Tt) {
        const float srow = part[(tid >> 2) * 8 + (tid & 3) * 2]
                         + part[(tid >> 2) * 8 + (tid & 3) * 2 + 1];
        out_alpha[(size_t)n * Tt + tid] = __expf(srow - m) * inv;
    }
}

extern "C" void kernel_launch(void* const* d_in, const int* in_sizes, int n_in,
                              void* d_out, int out_size)
{
    const float* h       = (const float*)d_in[0];   // [N, T, D] fp32
    const float* w_score = (const float*)d_in[1];   // [D] fp32

    float* out        = (float*)d_out;
    float* out_pooled = out;                        // [N, D]
    float* out_alpha  = out + (size_t)Nn * Dd;      // [N, T]

    cudaFuncSetAttribute(attn_pool_deep2,
                         cudaFuncAttributeMaxDynamicSharedMemorySize, SMEM_BYTES);

    attn_pool_deep2<<<Nn, THREADS, SMEM_BYTES>>>(h, w_score, out_pooled, out_alpha);
}

// round 14
// speedup vs baseline: 1.0529x; 1.0018x over previous
#include <cuda_runtime.h>
#include <cuda_bf16.h>
#include <cstdint>
#include <math.h>

// Shape fixed by reference: N=4096, T=64, D=1024, fp32.
#define Nn 4096
#define Tt 64
#define Dd 1024
#define THREADS 256          // 8 warps
#define TILE 4               // t-rows per tile (16 KB chunk); 16 tiles per n
#define NTILES 16
#define NBUF 3
#define TILE_BYTES (TILE * Dd * 4)   // 16384

// smem layout (bytes):
//   [0,24)      mbar[3]
//   [32,544)    part[16][8] : per-tile half-row dot partials (indexed by f)
//   [1024, 1024+3*16384) triple buffers
#define SMEM_MBAR_OFF   0
#define SMEM_PART_OFF   32
#define SMEM_BUF_OFF    1024
#define SMEM_BYTES      (SMEM_BUF_OFF + NBUF * TILE_BYTES)   // 50176 -> 4 CTA/SM

__device__ __forceinline__ uint32_t smem_u32(const void* p) {
    uint32_t a;
    asm("{ .reg .u64 t; cvta.to.shared.u64 t, %1; cvt.u32.u64 %0, t; }" : "=r"(a) : "l"(p));
    return a;
}
__device__ __forceinline__ void mbar_init(uint32_t mbar, uint32_t count) {
    asm volatile("mbarrier.init.shared.b64 [%0], %1;" :: "r"(mbar), "r"(count) : "memory");
}
__device__ __forceinline__ void mbar_expect_tx(uint32_t mbar, uint32_t bytes) {
    asm volatile("mbarrier.arrive.expect_tx.shared.b64 _, [%0], %1;" :: "r"(mbar), "r"(bytes) : "memory");
}
__device__ __forceinline__ void bulk_copy_g2s(uint32_t dst_smem, const void* src_gmem,
                                              uint32_t bytes, uint32_t mbar) {
    asm volatile(
        "cp.async.bulk.shared::cluster.global.mbarrier::complete_tx::bytes [%0], [%1], %2, [%3];"
        :: "r"(dst_smem), "l"(src_gmem), "r"(bytes), "r"(mbar) : "memory");
}
__device__ __forceinline__ void mbar_wait_parity(uint32_t mbar, uint32_t parity) {
    uint32_t done;
    asm volatile(
        "{\n\t.reg .pred p;\n\t"
        "mbarrier.try_wait.parity.acquire.cta.shared::cta.b64 p, [%1], %2;\n\t"
        "selp.b32 %0, 1, 0, p;\n\t}"
        : "=r"(done) : "r"(mbar), "r"(parity) : "memory");
    if (!done) {
        asm volatile(
            "{\n\t.reg .pred P1;\n\t"
            "WL_%=:\n\t"
            "mbarrier.try_wait.parity.acquire.cta.shared::cta.b64 P1, [%0], %1, 0x989680;\n\t"
            "@P1 bra.uni WD_%=;\n\t"
            "bra.uni WL_%=;\n\t"
            "WD_%=:\n\t}"
            :: "r"(mbar), "r"(parity) : "memory");
    }
}

__global__ __launch_bounds__(THREADS, 4)
void attn_pool_wreg(const float* __restrict__ h,
                    const float* __restrict__ w_score,
                    float* __restrict__ out_pooled,
                    float* __restrict__ out_alpha)
{
    extern __shared__ __align__(16) char smem_raw[];
    float*         part  = (float*)(smem_raw + SMEM_PART_OFF);    // [16][8]
    const uint32_t mbar_b = smem_u32(smem_raw + SMEM_MBAR_OFF);
    const uint32_t buf_s  = smem_u32(smem_raw + SMEM_BUF_OFF);

    const int n    = blockIdx.x;
    const int tid  = threadIdx.x;
    const int warp = tid >> 5;
    const int lane = tid & 31;
    const int row  = warp >> 1;      // tile-row this warp scores
    const int half = warp & 1;       // which 512-float half of the row

    const char* src = (const char*)(h + (size_t)n * (Tt * Dd));

    // ---- w_score slice for this warp's half-row dot: 4 float4, register-resident ----
    const float4* w4 = (const float4*)w_score;
    float4 wreg[4];
    #pragma unroll
    for (int j = 0; j < 4; j++)
        wreg[j] = __ldg(w4 + half * 128 + lane + 32 * j);

    if (tid == 0) {
        mbar_init(mbar_b,      1);
        mbar_init(mbar_b + 8,  1);
        mbar_init(mbar_b + 16, 1);
    }
    __syncthreads();
    if (tid == 0) {
        #pragma unroll
        for (int p = 0; p < NBUF; p++) {
            mbar_expect_tx(mbar_b + p * 8, TILE_BYTES);
            bulk_copy_g2s(buf_s + p * TILE_BYTES, src + (size_t)p * TILE_BYTES,
                          TILE_BYTES, mbar_b + p * 8);
        }
    }

    float m = -INFINITY, Z = 0.0f;               // redundant in all threads
    float4 acc = make_float4(0.f, 0.f, 0.f, 0.f);

    #pragma unroll
    for (int f = 0; f < NTILES; f++) {
        const int b   = f % NBUF;                // compile-time constants after unroll
        const int par = (f / NBUF) & 1;
        const uint32_t mb = mbar_b + b * 8;
        const float4*  bp = (const float4*)(smem_raw + SMEM_BUF_OFF + b * TILE_BYTES);

        mbar_wait_parity(mb, par);

        // ---- pooling slab into regs (tid-slice, 4x LDS.128 conflict-free) ----
        float4 v[TILE];
        #pragma unroll
        for (int i = 0; i < TILE; i++)
            v[i] = bp[i * 256 + tid];

        // ---- warp w: half-row dot, w from registers ----
        {
            const float4* rowp = bp + row * 256 + half * 128;
            float d0 = 0.f, d1 = 0.f, d2 = 0.f, d3 = 0.f;
            #pragma unroll
            for (int j = 0; j < 4; j++) {
                float4 x = rowp[lane + 32 * j];
                d0 = fmaf(x.x, wreg[j].x, d0);
                d1 = fmaf(x.y, wreg[j].y, d1);
                d2 = fmaf(x.z, wreg[j].z, d2);
                d3 = fmaf(x.w, wreg[j].w, d3);
            }
            float d = (d0 + d1) + (d2 + d3);
            #pragma unroll
            for (int off = 16; off > 0; off >>= 1)
                d += __shfl_xor_sync(0xFFFFFFFFu, d, off);
            if (lane == 0)
                part[f * 8 + row * 2 + half] = d;
        }
        __syncthreads();   // part[f] ready; all buffer-b reads complete

        // ---- refill this buffer for tile f+3 (2 tile-periods of slack) ----
        if (tid == 0 && f + NBUF < NTILES) {
            mbar_expect_tx(mb, TILE_BYTES);
            bulk_copy_g2s(buf_s + b * TILE_BYTES,
                          src + (size_t)(f + NBUF) * TILE_BYTES, TILE_BYTES, mb);
        }

        // ---- assemble 4 scores (2 broadcast LDS.128) ----
        const float4 p0 = *((const float4*)(part + f * 8));
        const float4 p1 = *((const float4*)(part + f * 8) + 1);
        float s[TILE] = { p0.x + p0.y, p0.z + p0.w, p1.x + p1.y, p1.z + p1.w };

        // ---- redundant online softmax ----
        const float tmax = fmaxf(fmaxf(s[0], s[1]), fmaxf(s[2], s[3]));
        const float newm = fmaxf(m, tmax);
        const float sc   = __expf(m - newm);
        float e[TILE], esum = 0.0f;
        #pragma unroll
        for (int i = 0; i < TILE; i++) { e[i] = __expf(s[i] - newm); esum += e[i]; }
        Z = Z * sc + esum;
        m = newm;

        float ax = acc.x * sc, ay = acc.y * sc, az = acc.z * sc, aw = acc.w * sc;
        #pragma unroll
        for (int i = 0; i < TILE; i++) {
            ax = fmaf(e[i], v[i].x, ax);
            ay = fmaf(e[i], v[i].y, ay);
            az = fmaf(e[i], v[i].z, az);
            aw = fmaf(e[i], v[i].w, aw);
        }
        acc = make_float4(ax, ay, az, aw);
    }

    // ---- finalize ----
    const float inv = 1.0f / Z;
    ((float4*)(out_pooled + (size_t)n * Dd))[tid] =
        make_float4(acc.x * inv, acc.y * inv, acc.z * inv, acc.w * inv);
    // alpha from part: score[t] = part[(t>>2)*8 + (t&3)*2] + part[(t>>2)*8 + (t&3)*2 + 1]
    if (tid < Tt) {
        const float srow = part[(tid >> 2) * 8 + (tid & 3) * 2]
                         + part[(tid >> 2) * 8 + (tid & 3) * 2 + 1];
        out_alpha[(size_t)n * Tt + tid] = __expf(srow - m) * inv;
    }
}

extern "C" void kernel_launch(void* const* d_in, const int* in_sizes, int n_in,
                              void* d_out, int out_size)
{
    const float* h       = (const float*)d_in[0];   // [N, T, D] fp32
    const float* w_score = (const float*)d_in[1];   // [D] fp32

    float* out        = (float*)d_out;
    float* out_pooled = out;                        // [N, D]
    float* out_alpha  = out + (size_t)Nn * Dd;      // [N, T]

    cudaFuncSetAttribute(attn_pool_wreg,
                         cudaFuncAttributeMaxDynamicSharedMemorySize, SMEM_BYTES);

    attn_pool_wreg<<<Nn, THREADS, SMEM_BYTES>>>(h, w_score, out_pooled, out_alpha);
}

// round 15
// speedup vs baseline: 1.0674x; 1.0138x over previous
#include <cuda_runtime.h>
#include <cuda_bf16.h>
#include <cstdint>
#include <math.h>

// Shape fixed by reference: N=4096, T=64, D=1024, fp32.
#define Nn 4096
#define Tt 64
#define Dd 1024
#define THREADS 256          // 8 warps
#define TILE 4               // t-rows per tile (16 KB chunk); 16 tiles per n
#define NTILES 16
#define NBUF 3
#define TILE_BYTES (TILE * Dd * 4)   // 16384

// smem layout (bytes):
//   [0,24)      mbar[3]
//   [32,544)    part[16][8] : per-tile half-row dot partials (indexed by f)
//   [1024, 1024+3*16384) triple buffers
#define SMEM_MBAR_OFF   0
#define SMEM_PART_OFF   32
#define SMEM_BUF_OFF    1024
#define SMEM_BYTES      (SMEM_BUF_OFF + NBUF * TILE_BYTES)   // 50176 -> 4 CTA/SM

__device__ __forceinline__ uint32_t smem_u32(const void* p) {
    uint32_t a;
    asm("{ .reg .u64 t; cvta.to.shared.u64 t, %1; cvt.u32.u64 %0, t; }" : "=r"(a) : "l"(p));
    return a;
}
__device__ __forceinline__ void mbar_init(uint32_t mbar, uint32_t count) {
    asm volatile("mbarrier.init.shared.b64 [%0], %1;" :: "r"(mbar), "r"(count) : "memory");
}
__device__ __forceinline__ void mbar_expect_tx(uint32_t mbar, uint32_t bytes) {
    asm volatile("mbarrier.arrive.expect_tx.shared.b64 _, [%0], %1;" :: "r"(mbar), "r"(bytes) : "memory");
}
__device__ __forceinline__ void bulk_copy_g2s(uint32_t dst_smem, const void* src_gmem,
                                              uint32_t bytes, uint32_t mbar) {
    asm volatile(
        "cp.async.bulk.shared::cluster.global.mbarrier::complete_tx::bytes [%0], [%1], %2, [%3];"
        :: "r"(dst_smem), "l"(src_gmem), "r"(bytes), "r"(mbar) : "memory");
}
__device__ __forceinline__ void mbar_wait_parity(uint32_t mbar, uint32_t parity) {
    uint32_t done;
    asm volatile(
        "{\n\t.reg .pred p;\n\t"
        "mbarrier.try_wait.parity.acquire.cta.shared::cta.b64 p, [%1], %2;\n\t"
        "selp.b32 %0, 1, 0, p;\n\t}"
        : "=r"(done) : "r"(mbar), "r"(parity) : "memory");
    if (!done) {
        asm volatile(
            "{\n\t.reg .pred P1;\n\t"
            "WL_%=:\n\t"
            "mbarrier.try_wait.parity.acquire.cta.shared::cta.b64 P1, [%0], %1, 0x989680;\n\t"
            "@P1 bra.uni WD_%=;\n\t"
            "bra.uni WL_%=;\n\t"
            "WD_%=:\n\t}"
            :: "r"(mbar), "r"(parity) : "memory");
    }
}

__global__ __launch_bounds__(THREADS, 4)
void attn_pool_final(const float* __restrict__ h,
                     const float* __restrict__ w_score,
                     float* __restrict__ out_pooled,
                     float* __restrict__ out_alpha)
{
    extern __shared__ __align__(16) char smem_raw[];
    float*         part   = (float*)(smem_raw + SMEM_PART_OFF);    // [16][8]
    const uint32_t mbar_b = smem_u32(smem_raw + SMEM_MBAR_OFF);
    const uint32_t buf_s  = smem_u32(smem_raw + SMEM_BUF_OFF);

    const int n    = blockIdx.x;
    const int tid  = threadIdx.x;
    const int warp = tid >> 5;
    const int lane = tid & 31;
    const int row  = warp >> 1;      // tile-row this warp scores
    const int half = warp & 1;       // which 512-float half of the row

    const char* src = (const char*)(h + (size_t)n * (Tt * Dd));

    // ---- w_score slice for this warp's half-row dot: 4 float4, register-resident ----
    const float4* w4 = (const float4*)w_score;
    float4 wreg[4];
    #pragma unroll
    for (int j = 0; j < 4; j++)
        wreg[j] = __ldg(w4 + half * 128 + lane + 32 * j);

    if (tid == 0) {
        mbar_init(mbar_b,      1);
        mbar_init(mbar_b + 8,  1);
        mbar_init(mbar_b + 16, 1);
    }
    __syncthreads();
    if (tid == 0) {
        #pragma unroll
        for (int p = 0; p < NBUF; p++) {
            mbar_expect_tx(mbar_b + p * 8, TILE_BYTES);
            bulk_copy_g2s(buf_s + p * TILE_BYTES, src + (size_t)p * TILE_BYTES,
                          TILE_BYTES, mbar_b + p * 8);
        }
    }

    float m = -INFINITY, Z = 0.0f;               // redundant in all threads
    float4 acc = make_float4(0.f, 0.f, 0.f, 0.f);

    #pragma unroll
    for (int f = 0; f < NTILES; f++) {
        const int b   = f % NBUF;                // compile-time constants after unroll
        const int par = (f / NBUF) & 1;
        const uint32_t mb = mbar_b + b * 8;
        const float4*  bp = (const float4*)(smem_raw + SMEM_BUF_OFF + b * TILE_BYTES);

        mbar_wait_parity(mb, par);

        // ---- pooling slab into regs (tid-slice, 4x LDS.128 conflict-free) ----
        float4 v[TILE];
        #pragma unroll
        for (int i = 0; i < TILE; i++)
            v[i] = bp[i * 256 + tid];

        // ---- warp w: half-row dot, w from registers ----
        {
            const float4* rowp = bp + row * 256 + half * 128;
            float d0 = 0.f, d1 = 0.f, d2 = 0.f, d3 = 0.f;
            #pragma unroll
            for (int j = 0; j < 4; j++) {
                float4 x = rowp[lane + 32 * j];
                d0 = fmaf(x.x, wreg[j].x, d0);
                d1 = fmaf(x.y, wreg[j].y, d1);
                d2 = fmaf(x.z, wreg[j].z, d2);
                d3 = fmaf(x.w, wreg[j].w, d3);
            }
            float d = (d0 + d1) + (d2 + d3);
            #pragma unroll
            for (int off = 16; off > 0; off >>= 1)
                d += __shfl_xor_sync(0xFFFFFFFFu, d, off);
            if (lane == 0)
                part[f * 8 + row * 2 + half] = d;
        }
        __syncthreads();   // part[f] ready; all buffer-b reads complete

        // ---- refill this buffer for tile f+3 (2 tile-periods of slack) ----
        if (tid == 0 && f + NBUF < NTILES) {
            mbar_expect_tx(mb, TILE_BYTES);
            bulk_copy_g2s(buf_s + b * TILE_BYTES,
                          src + (size_t)(f + NBUF) * TILE_BYTES, TILE_BYTES, mb);
        }

        // ---- assemble 4 scores (2 broadcast LDS.128) ----
        const float4 p0 = *((const float4*)(part + f * 8));
        const float4 p1 = *((const float4*)(part + f * 8) + 1);
        float s[TILE] = { p0.x + p0.y, p0.z + p0.w, p1.x + p1.y, p1.z + p1.w };

        // ---- redundant online softmax ----
        const float tmax = fmaxf(fmaxf(s[0], s[1]), fmaxf(s[2], s[3]));
        const float newm = fmaxf(m, tmax);
        const float sc   = __expf(m - newm);
        float e[TILE], esum = 0.0f;
        #pragma unroll
        for (int i = 0; i < TILE; i++) { e[i] = __expf(s[i] - newm); esum += e[i]; }
        Z = Z * sc + esum;
        m = newm;

        float ax = acc.x * sc, ay = acc.y * sc, az = acc.z * sc, aw = acc.w * sc;
        #pragma unroll
        for (int i = 0; i < TILE; i++) {
            ax = fmaf(e[i], v[i].x, ax);
            ay = fmaf(e[i], v[i].y, ay);
            az = fmaf(e[i], v[i].z, az);
            aw = fmaf(e[i], v[i].w, aw);
        }
        acc = make_float4(ax, ay, az, aw);
    }

    // ---- finalize (streaming stores: outputs have no reuse, keep them out of L2) ----
    const float inv = 1.0f / Z;
    __stcs((float4*)(out_pooled + (size_t)n * Dd) + tid,
           make_float4(acc.x * inv, acc.y * inv, acc.z * inv, acc.w * inv));
    // alpha from part: score[t] = part[(t>>2)*8 + (t&3)*2] + part[(t>>2)*8 + (t&3)*2 + 1]
    if (tid < Tt) {
        const float srow = part[(tid >> 2) * 8 + (tid & 3) * 2]
                         + part[(tid >> 2) * 8 + (tid & 3) * 2 + 1];
        __stcs(out_alpha + (size_t)n * Tt + tid, __expf(srow - m) * inv);
    }
}

extern "C" void kernel_launch(void* const* d_in, const int* in_sizes, int n_in,
                              void* d_out, int out_size)
{
    const float* h       = (const float*)d_in[0];   // [N, T, D] fp32
    const float* w_score = (const float*)d_in[1];   // [D] fp32

    float* out        = (float*)d_out;
    float* out_pooled = out;                        // [N, D]
    float* out_alpha  = out + (size_t)Nn * Dd;      // [N, T]

    cudaFuncSetAttribute(attn_pool_final,
                         cudaFuncAttributeMaxDynamicSharedMemorySize, SMEM_BYTES);

    attn_pool_final<<<Nn, THREADS, SMEM_BYTES>>>(h, w_score, out_pooled, out_alpha);
}

// round 16
// speedup vs baseline: 1.0786x; 1.0104x over previous
#include <cuda_runtime.h>
#include <cuda_bf16.h>
#include <cstdint>
#include <math.h>

// Shape fixed by reference: N=4096, T=64, D=1024, fp32.
#define Nn 4096
#define Tt 64
#define Dd 1024
#define THREADS 256          // 8 warps
#define TILE 4               // t-rows per tile (16 KB chunk); 16 tiles per n
#define NTILES 16
#define NBUF 3
#define TILE_BYTES (TILE * Dd * 4)   // 16384

// smem layout (bytes):
//   [0,24)      mbar[3]
//   [32,544)    part[16][8] : per-tile half-row dot partials (indexed by f)
//   [1024, 1024+3*16384) triple buffers
#define SMEM_MBAR_OFF   0
#define SMEM_PART_OFF   32
#define SMEM_BUF_OFF    1024
#define SMEM_BYTES      (SMEM_BUF_OFF + NBUF * TILE_BYTES)   // 50176 -> 4 CTA/SM

__device__ __forceinline__ uint32_t smem_u32(const void* p) {
    uint32_t a;
    asm("{ .reg .u64 t; cvta.to.shared.u64 t, %1; cvt.u32.u64 %0, t; }" : "=r"(a) : "l"(p));
    return a;
}
__device__ __forceinline__ void mbar_init(uint32_t mbar, uint32_t count) {
    asm volatile("mbarrier.init.shared.b64 [%0], %1;" :: "r"(mbar), "r"(count) : "memory");
}
__device__ __forceinline__ void mbar_expect_tx(uint32_t mbar, uint32_t bytes) {
    asm volatile("mbarrier.arrive.expect_tx.shared.b64 _, [%0], %1;" :: "r"(mbar), "r"(bytes) : "memory");
}
// evict_first policy for the no-reuse read stream
__device__ __forceinline__ uint64_t make_evict_first_policy() {
    uint64_t pol;
    asm("createpolicy.fractional.L2::evict_first.b64 %0, 1.0;" : "=l"(pol));
    return pol;
}
__device__ __forceinline__ void bulk_copy_g2s_ef(uint32_t dst_smem, const void* src_gmem,
                                                 uint32_t bytes, uint32_t mbar, uint64_t pol) {
    asm volatile(
        "cp.async.bulk.shared::cluster.global.mbarrier::complete_tx::bytes.L2::cache_hint"
        " [%0], [%1], %2, [%3], %4;"
        :: "r"(dst_smem), "l"(src_gmem), "r"(bytes), "r"(mbar), "l"(pol) : "memory");
}
__device__ __forceinline__ void mbar_wait_parity(uint32_t mbar, uint32_t parity) {
    uint32_t done;
    asm volatile(
        "{\n\t.reg .pred p;\n\t"
        "mbarrier.try_wait.parity.acquire.cta.shared::cta.b64 p, [%1], %2;\n\t"
        "selp.b32 %0, 1, 0, p;\n\t}"
        : "=r"(done) : "r"(mbar), "r"(parity) : "memory");
    if (!done) {
        asm volatile(
            "{\n\t.reg .pred P1;\n\t"
            "WL_%=:\n\t"
            "mbarrier.try_wait.parity.acquire.cta.shared::cta.b64 P1, [%0], %1, 0x989680;\n\t"
            "@P1 bra.uni WD_%=;\n\t"
            "bra.uni WL_%=;\n\t"
            "WD_%=:\n\t}"
            :: "r"(mbar), "r"(parity) : "memory");
    }
}

__global__ __launch_bounds__(THREADS, 4)
void attn_pool_final2(const float* __restrict__ h,
                      const float* __restrict__ w_score,
                      float* __restrict__ out_pooled,
                      float* __restrict__ out_alpha)
{
    extern __shared__ __align__(16) char smem_raw[];
    float*         part   = (float*)(smem_raw + SMEM_PART_OFF);    // [16][8]
    const uint32_t mbar_b = smem_u32(smem_raw + SMEM_MBAR_OFF);
    const uint32_t buf_s  = smem_u32(smem_raw + SMEM_BUF_OFF);

    const int n    = blockIdx.x;
    const int tid  = threadIdx.x;
    const int warp = tid >> 5;
    const int lane = tid & 31;
    const int row  = warp >> 1;      // tile-row this warp scores
    const int half = warp & 1;       // which 512-float half of the row

    const char* src = (const char*)(h + (size_t)n * (Tt * Dd));

    // ---- w_score slice for this warp's half-row dot: 4 float4, register-resident ----
    const float4* w4 = (const float4*)w_score;
    float4 wreg[4];
    #pragma unroll
    for (int j = 0; j < 4; j++)
        wreg[j] = __ldg(w4 + half * 128 + lane + 32 * j);

    const uint64_t pol = make_evict_first_policy();

    if (tid == 0) {
        mbar_init(mbar_b,      1);
        mbar_init(mbar_b + 8,  1);
        mbar_init(mbar_b + 16, 1);
    }
    __syncthreads();
    if (tid == 0) {
        #pragma unroll
        for (int p = 0; p < NBUF; p++) {
            mbar_expect_tx(mbar_b + p * 8, TILE_BYTES);
            bulk_copy_g2s_ef(buf_s + p * TILE_BYTES, src + (size_t)p * TILE_BYTES,
                             TILE_BYTES, mbar_b + p * 8, pol);
        }
    }

    float m = -INFINITY, Z = 0.0f;               // redundant in all threads
    float4 acc = make_float4(0.f, 0.f, 0.f, 0.f);

    #pragma unroll
    for (int f = 0; f < NTILES; f++) {
        const int b   = f % NBUF;                // compile-time constants after unroll
        const int par = (f / NBUF) & 1;
        const uint32_t mb = mbar_b + b * 8;
        const float4*  bp = (const float4*)(smem_raw + SMEM_BUF_OFF + b * TILE_BYTES);

        mbar_wait_parity(mb, par);

        // ---- pooling slab into regs (tid-slice, 4x LDS.128 conflict-free) ----
        float4 v[TILE];
        #pragma unroll
        for (int i = 0; i < TILE; i++)
            v[i] = bp[i * 256 + tid];

        // ---- warp w: half-row dot, w from registers ----
        {
            const float4* rowp = bp + row * 256 + half * 128;
            float d0 = 0.f, d1 = 0.f, d2 = 0.f, d3 = 0.f;
            #pragma unroll
            for (int j = 0; j < 4; j++) {
                float4 x = rowp[lane + 32 * j];
                d0 = fmaf(x.x, wreg[j].x, d0);
                d1 = fmaf(x.y, wreg[j].y, d1);
                d2 = fmaf(x.z, wreg[j].z, d2);
                d3 = fmaf(x.w, wreg[j].w, d3);
            }
            float d = (d0 + d1) + (d2 + d3);
            #pragma unroll
            for (int off = 16; off > 0; off >>= 1)
                d += __shfl_xor_sync(0xFFFFFFFFu, d, off);
            if (lane == 0)
                part[f * 8 + row * 2 + half] = d;
        }
        __syncthreads();   // part[f] ready; all buffer-b reads complete

        // ---- refill this buffer for tile f+3 (2 tile-periods of slack) ----
        if (tid == 0 && f + NBUF < NTILES) {
            mbar_expect_tx(mb, TILE_BYTES);
            bulk_copy_g2s_ef(buf_s + b * TILE_BYTES,
                             src + (size_t)(f + NBUF) * TILE_BYTES, TILE_BYTES, mb, pol);
        }

        // ---- assemble 4 scores (2 broadcast LDS.128) ----
        const float4 p0 = *((const float4*)(part + f * 8));
        const float4 p1 = *((const float4*)(part + f * 8) + 1);
        float s[TILE] = { p0.x + p0.y, p0.z + p0.w, p1.x + p1.y, p1.z + p1.w };

        // ---- redundant online softmax ----
        const float tmax = fmaxf(fmaxf(s[0], s[1]), fmaxf(s[2], s[3]));
        const float newm = fmaxf(m, tmax);
        const float sc   = __expf(m - newm);
        float e[TILE], esum = 0.0f;
        #pragma unroll
        for (int i = 0; i < TILE; i++) { e[i] = __expf(s[i] - newm); esum += e[i]; }
        Z = Z * sc + esum;
        m = newm;

        float ax = acc.x * sc, ay = acc.y * sc, az = acc.z * sc, aw = acc.w * sc;
        #pragma unroll
        for (int i = 0; i < TILE; i++) {
            ax = fmaf(e[i], v[i].x, ax);
            ay = fmaf(e[i], v[i].y, ay);
            az = fmaf(e[i], v[i].z, az);
            aw = fmaf(e[i], v[i].w, aw);
        }
        acc = make_float4(ax, ay, az, aw);
    }

    // ---- finalize (streaming stores: outputs have no reuse) ----
    const float inv = 1.0f / Z;
    __stcs((float4*)(out_pooled + (size_t)n * Dd) + tid,
           make_float4(acc.x * inv, acc.y * inv, acc.z * inv, acc.w * inv));
    // alpha from part: score[t] = part[(t>>2)*8 + (t&3)*2] + part[(t>>2)*8 + (t&3)*2 + 1]
    if (tid < Tt) {
        const float srow = part[(tid >> 2) * 8 + (tid & 3) * 2]
                         + part[(tid >> 2) * 8 + (tid & 3) * 2 + 1];
        __stcs(out_alpha + (size_t)n * Tt + tid, __expf(srow - m) * inv);
    }
}

extern "C" void kernel_launch(void* const* d_in, const int* in_sizes, int n_in,
                              void* d_out, int out_size)
{
    const float* h       = (const float*)d_in[0];   // [N, T, D] fp32
    const float* w_score = (const float*)d_in[1];   // [D] fp32

    float* out        = (float*)d_out;
    float* out_pooled = out;                        // [N, D]
    float* out_alpha  = out + (size_t)Nn * Dd;      // [N, T]

    cudaFuncSetAttribute(attn_pool_final2,
                         cudaFuncAttributeMaxDynamicSharedMemorySize, SMEM_BYTES);

    attn_pool_final2<<<Nn, THREADS, SMEM_BYTES>>>(h, w_score, out_pooled, out_alpha);
}

// round 17
// speedup vs baseline: 1.1127x; 1.0317x over previous
#include <cuda_runtime.h>
#include <cuda_bf16.h>
#include <cstdint>
#include <math.h>

// Shape fixed by reference: N=4096, T=64, D=1024, fp32.
#define Nn 4096
#define Tt 64
#define Dd 1024
#define THREADS 256          // 8 warps; warp w: row=w>>2, quarter=w&3
#define TILE 2               // t-rows per tile (8 KB chunk); 32 tiles per n
#define NTILES 32
#define NBUF 4
#define TILE_BYTES (TILE * Dd * 4)   // 8192

// smem layout (bytes):
//   [0,32)      mbar[4]
//   [32,1056)   part[32][8] : per-tile quarter-row dot partials (indexed by f)
//   [2048, 2048+4*8192) quad buffers
#define SMEM_MBAR_OFF   0
#define SMEM_PART_OFF   32
#define SMEM_BUF_OFF    2048
#define SMEM_BYTES      (SMEM_BUF_OFF + NBUF * TILE_BYTES)   // 34816 -> 5 CTA/SM (reg-capped)

__device__ __forceinline__ uint32_t smem_u32(const void* p) {
    uint32_t a;
    asm("{ .reg .u64 t; cvta.to.shared.u64 t, %1; cvt.u32.u64 %0, t; }" : "=r"(a) : "l"(p));
    return a;
}
__device__ __forceinline__ void mbar_init(uint32_t mbar, uint32_t count) {
    asm volatile("mbarrier.init.shared.b64 [%0], %1;" :: "r"(mbar), "r"(count) : "memory");
}
__device__ __forceinline__ void mbar_expect_tx(uint32_t mbar, uint32_t bytes) {
    asm volatile("mbarrier.arrive.expect_tx.shared.b64 _, [%0], %1;" :: "r"(mbar), "r"(bytes) : "memory");
}
__device__ __forceinline__ uint64_t make_evict_first_policy() {
    uint64_t pol;
    asm("createpolicy.fractional.L2::evict_first.b64 %0, 1.0;" : "=l"(pol));
    return pol;
}
__device__ __forceinline__ void bulk_copy_g2s_ef(uint32_t dst_smem, const void* src_gmem,
                                                 uint32_t bytes, uint32_t mbar, uint64_t pol) {
    asm volatile(
        "cp.async.bulk.shared::cluster.global.mbarrier::complete_tx::bytes.L2::cache_hint"
        " [%0], [%1], %2, [%3], %4;"
        :: "r"(dst_smem), "l"(src_gmem), "r"(bytes), "r"(mbar), "l"(pol) : "memory");
}
__device__ __forceinline__ void mbar_wait_parity(uint32_t mbar, uint32_t parity) {
    uint32_t done;
    asm volatile(
        "{\n\t.reg .pred p;\n\t"
        "mbarrier.try_wait.parity.acquire.cta.shared::cta.b64 p, [%1], %2;\n\t"
        "selp.b32 %0, 1, 0, p;\n\t}"
        : "=r"(done) : "r"(mbar), "r"(parity) : "memory");
    if (!done) {
        asm volatile(
            "{\n\t.reg .pred P1;\n\t"
            "WL_%=:\n\t"
            "mbarrier.try_wait.parity.acquire.cta.shared::cta.b64 P1, [%0], %1, 0x989680;\n\t"
            "@P1 bra.uni WD_%=;\n\t"
            "bra.uni WL_%=;\n\t"
            "WD_%=:\n\t}"
            :: "r"(mbar), "r"(parity) : "memory");
    }
}

__global__ __launch_bounds__(THREADS, 5)
void attn_pool_occ5(const float* __restrict__ h,
                    const float* __restrict__ w_score,
                    float* __restrict__ out_pooled,
                    float* __restrict__ out_alpha)
{
    extern __shared__ __align__(16) char smem_raw[];
    float*         part   = (float*)(smem_raw + SMEM_PART_OFF);    // [32][8]
    const uint32_t mbar_b = smem_u32(smem_raw + SMEM_MBAR_OFF);
    const uint32_t buf_s  = smem_u32(smem_raw + SMEM_BUF_OFF);

    const int n    = blockIdx.x;
    const int tid  = threadIdx.x;
    const int warp = tid >> 5;
    const int lane = tid & 31;
    const int row  = warp >> 2;      // tile-row this warp scores (0..1)
    const int qtr  = warp & 3;       // which 256-float quarter of the row

    const char* src = (const char*)(h + (size_t)n * (Tt * Dd));

    // ---- w_score slice for this warp's quarter-row dot: 2 float4, register-resident ----
    const float4* w4 = (const float4*)w_score;
    float4 wreg[2];
    #pragma unroll
    for (int j = 0; j < 2; j++)
        wreg[j] = __ldg(w4 + qtr * 64 + lane + 32 * j);

    const uint64_t pol = make_evict_first_policy();

    if (tid < NBUF)
        mbar_init(mbar_b + tid * 8, 1);
    __syncthreads();
    if (tid == 0) {
        #pragma unroll
        for (int p = 0; p < NBUF; p++) {
            mbar_expect_tx(mbar_b + p * 8, TILE_BYTES);
            bulk_copy_g2s_ef(buf_s + p * TILE_BYTES, src + (size_t)p * TILE_BYTES,
                             TILE_BYTES, mbar_b + p * 8, pol);
        }
    }

    float m = -INFINITY, Z = 0.0f;               // redundant in all threads
    float4 acc = make_float4(0.f, 0.f, 0.f, 0.f);

    // 4 groups of 8: b = k % 4 and par = (k/4)&1 are group-invariant compile-time
    #pragma unroll 1
    for (int g = 0; g < 4; g++) {
        #pragma unroll
        for (int k = 0; k < 8; k++) {
            const int f   = g * 8 + k;               // runtime only via g (cheap)
            const int b   = k % NBUF;                // compile-time
            const int par = (k / NBUF) & 1;          // compile-time (groups flip by 2)
            const uint32_t mb = mbar_b + b * 8;
            const float4*  bp = (const float4*)(smem_raw + SMEM_BUF_OFF + b * TILE_BYTES);

            mbar_wait_parity(mb, par);

            // ---- pooling slab into regs (tid-slice, 2x LDS.128) ----
            float4 v[TILE];
            #pragma unroll
            for (int i = 0; i < TILE; i++)
                v[i] = bp[i * 256 + tid];

            // ---- warp w: quarter-row dot, w from registers ----
            {
                const float4* rowp = bp + row * 256 + qtr * 64;
                float d0 = 0.f, d1 = 0.f, d2 = 0.f, d3 = 0.f;
                #pragma unroll
                for (int j = 0; j < 2; j++) {
                    float4 x = rowp[lane + 32 * j];
                    d0 = fmaf(x.x, wreg[j].x, d0);
                    d1 = fmaf(x.y, wreg[j].y, d1);
                    d2 = fmaf(x.z, wreg[j].z, d2);
                    d3 = fmaf(x.w, wreg[j].w, d3);
                }
                float d = (d0 + d1) + (d2 + d3);
                #pragma unroll
                for (int off = 16; off > 0; off >>= 1)
                    d += __shfl_xor_sync(0xFFFFFFFFu, d, off);
                if (lane == 0)
                    part[f * 8 + row * 4 + qtr] = d;
            }
            __syncthreads();   // part[f] ready; all buffer-b reads complete

            // ---- refill this buffer for tile f+4 (3 tile-periods slack) ----
            if (tid == 0 && f + NBUF < NTILES) {
                mbar_expect_tx(mb, TILE_BYTES);
                bulk_copy_g2s_ef(buf_s + b * TILE_BYTES,
                                 src + (size_t)(f + NBUF) * TILE_BYTES, TILE_BYTES, mb, pol);
            }

            // ---- assemble 2 scores (2 broadcast LDS.128) ----
            const float4 p0 = *((const float4*)(part + f * 8));       // row0 quarters
            const float4 p1 = *((const float4*)(part + f * 8) + 1);   // row1 quarters
            const float s0 = (p0.x + p0.y) + (p0.z + p0.w);
            const float s1 = (p1.x + p1.y) + (p1.z + p1.w);

            // ---- redundant online softmax over 2 rows ----
            const float newm = fmaxf(m, fmaxf(s0, s1));
            const float sc   = __expf(m - newm);
            const float e0   = __expf(s0 - newm);
            const float e1   = __expf(s1 - newm);
            Z = Z * sc + (e0 + e1);
            m = newm;

            acc.x = fmaf(e1, v[1].x, fmaf(e0, v[0].x, acc.x * sc));
            acc.y = fmaf(e1, v[1].y, fmaf(e0, v[0].y, acc.y * sc));
            acc.z = fmaf(e1, v[1].z, fmaf(e0, v[0].z, acc.z * sc));
            acc.w = fmaf(e1, v[1].w, fmaf(e0, v[0].w, acc.w * sc));
        }
    }

    // ---- finalize (streaming stores) ----
    const float inv = 1.0f / Z;
    __stcs((float4*)(out_pooled + (size_t)n * Dd) + tid,
           make_float4(acc.x * inv, acc.y * inv, acc.z * inv, acc.w * inv));
    // alpha: score[t] = sum of 4 quarters = horizontal sum of part4[t]
    if (tid < Tt) {
        const float4 q = ((const float4*)part)[tid];   // part4[f*2+row] == part4[t]
        const float srow = (q.x + q.y) + (q.z + q.w);
        __stcs(out_alpha + (size_t)n * Tt + tid, __expf(srow - m) * inv);
    }
}

extern "C" void kernel_launch(void* const* d_in, const int* in_sizes, int n_in,
                              void* d_out, int out_size)
{
    const float* h       = (const float*)d_in[0];   // [N, T, D] fp32
    const float* w_score = (const float*)d_in[1];   // [D] fp32

    float* out        = (float*)d_out;
    float* out_pooled = out;                        // [N, D]
    float* out_alpha  = out + (size_t)Nn * Dd;      // [N, T]

    cudaFuncSetAttribute(attn_pool_occ5,
                         cudaFuncAttributeMaxDynamicSharedMemorySize, SMEM_BYTES);

    attn_pool_occ5<<<Nn, THREADS, SMEM_BYTES>>>(h, w_score, out_pooled, out_alpha);
}